// round 10
// baseline (speedup 1.0000x reference)
#include <cuda_runtime.h>
#include <cuda_fp16.h>
#include <cstdint>
#include <cstddef>

// ---------------------------------------------------------------------------
// Geometry
// ---------------------------------------------------------------------------
static constexpr int KF = 4096;
static constexpr int NF = 14336;
static constexpr int MROWS = 256;         // batch rows
static constexpr int NTILE = 128;
static constexpr int NCTA = NF / NTILE;   // 112
static constexpr int KC = 64;             // k per stage
static constexpr int NITER = KF / KC;     // 64

// fp16 image of x, pre-swizzled as the A smem tile image:
// 64 tiles (one per 64-k chunk), each 256 rows x 128B = 32KB.
__device__ __align__(128) unsigned char g_xs[64 * 32768];

// SMEM: A 2 x 32768 | B 2 x 16384
static constexpr uint32_t SM_A = 0;
static constexpr uint32_t SM_B = 65536;
static constexpr uint32_t SM_TOTAL = 98304;

// ---------------------------------------------------------------------------
// Helpers
// ---------------------------------------------------------------------------
__device__ __forceinline__ __half2 u2h(uint32_t u) { return *reinterpret_cast<__half2*>(&u); }
__device__ __forceinline__ uint32_t h2u(__half2 h) { return *reinterpret_cast<uint32_t*>(&h); }

__device__ __forceinline__ void ldsm_x4(uint32_t (&r)[4], uint32_t addr) {
    asm volatile("ldmatrix.sync.aligned.m8n8.x4.shared.b16 {%0,%1,%2,%3}, [%4];"
                 : "=r"(r[0]), "=r"(r[1]), "=r"(r[2]), "=r"(r[3]) : "r"(addr));
}
__device__ __forceinline__ void ldsm_x4_t(uint32_t& r0, uint32_t& r1, uint32_t& r2, uint32_t& r3,
                                          uint32_t addr) {
    asm volatile("ldmatrix.sync.aligned.m8n8.x4.trans.shared.b16 {%0,%1,%2,%3}, [%4];"
                 : "=r"(r0), "=r"(r1), "=r"(r2), "=r"(r3) : "r"(addr));
}
// fp16-accumulate MMA (rt ~8/SMSP, 2x the fp32-accum rate)
__device__ __forceinline__ void mma16816_h(uint32_t (&c)[2], const uint32_t (&a)[4],
                                           uint32_t b0, uint32_t b1) {
    asm volatile("mma.sync.aligned.m16n8k16.row.col.f16.f16.f16.f16 "
                 "{%0,%1}, {%2,%3,%4,%5}, {%6,%7}, {%0,%1};"
                 : "+r"(c[0]), "+r"(c[1])
                 : "r"(a[0]), "r"(a[1]), "r"(a[2]), "r"(a[3]), "r"(b0), "r"(b1));
}

// ---------------------------------------------------------------------------
// Kernel 1: x fp32 -> fp16 pre-swizzled A tile images. 8 k per thread.
// byte(m, kl) = m*128 + (((kl>>3)^(m&7))<<4) + (kl&7)*2
// ---------------------------------------------------------------------------
__global__ __launch_bounds__(256) void prep_x_kernel(const float* __restrict__ x) {
    int idx = blockIdx.x * 256 + threadIdx.x;      // 131072 threads
    int m   = idx >> 9;
    int kl8 = (idx & 511) * 8;
    const float* xp = x + (size_t)m * KF + kl8;
    float4 v0 = *reinterpret_cast<const float4*>(xp);
    float4 v1 = *reinterpret_cast<const float4*>(xp + 4);
    uint4 o;
    o.x = h2u(__floats2half2_rn(v0.x, v0.y));
    o.y = h2u(__floats2half2_rn(v0.z, v0.w));
    o.z = h2u(__floats2half2_rn(v1.x, v1.y));
    o.w = h2u(__floats2half2_rn(v1.z, v1.w));
    int c = kl8 >> 6, kl = kl8 & 63;
    uint32_t off = (uint32_t)m * 128u + ((((uint32_t)(kl >> 3)) ^ (uint32_t)(m & 7)) << 4);
    *reinterpret_cast<uint4*>(g_xs + (size_t)c * 32768 + off) = o;
}

// ---------------------------------------------------------------------------
// Kernel 2: GEMM. 112 CTAs x 256 threads, 1 CTA/SM.
// 8 warps as 4(m) x 2(n); warp tile 64x64.
// fp16 accumulator chains of length 4 (k=64), flushed to fp32 each chunk.
// ---------------------------------------------------------------------------
__global__ __launch_bounds__(256, 1)
void gemm_kernel(const int* __restrict__ qk, const float* __restrict__ qs,
                 const float* __restrict__ qzb, const float* __restrict__ bias,
                 float* __restrict__ out) {
    extern __shared__ unsigned char smem[];
    const uint32_t sb = (uint32_t)__cvta_generic_to_shared(smem);
    const int t = threadIdx.x, lane = t & 31, w = t >> 5;
    const int wm = w >> 1, wn = w & 1;
    const int n0 = blockIdx.x * NTILE;

    // ---- dequant mapping ----
    const int nq = lane;
    const int kw = w;
    const uint32_t sts_base = (uint32_t)kw * 256u
                            + ((uint32_t)((nq >> 1) ^ kw) << 4) + (uint32_t)(nq & 1) * 8u;
    const int*   qbase = qk  + n0 + nq * 4;
    const float* sbase = qs  + n0 + nq * 4;
    const float* zbase = qzb + n0 + nq * 4;

    // ---- ldmatrix addressing ----
    const int l15 = lane & 15;
    const uint32_t sx = (uint32_t)(lane & 7);
    const uint32_t lq = (uint32_t)(lane >> 4);
    uint32_t a_row[4];
#pragma unroll
    for (int mb = 0; mb < 4; mb++)
        a_row[mb] = (uint32_t)(wm * 64 + mb * 16 + l15) * 128u;
    const uint32_t b_row = (uint32_t)l15 * 256u + (uint32_t)wn * 128u;

    float d[4][8][4];
#pragma unroll
    for (int mb = 0; mb < 4; mb++)
#pragma unroll
        for (int nb = 0; nb < 8; nb++)
#pragma unroll
            for (int i = 0; i < 4; i++) d[mb][nb][i] = 0.0f;

    int4 bq4[4];
    uint32_t s01, s23, z01, z23;

    auto prefetch_a = [&](int c, int st) {
        const unsigned char* asrc = g_xs + (size_t)c * 32768 + (size_t)t * 16;
        uint32_t adst = sb + SM_A + (uint32_t)st * 32768u + (uint32_t)t * 16u;
#pragma unroll
        for (int i = 0; i < 8; i++) {
            asm volatile("cp.async.cg.shared.global [%0], [%1], 16;"
                         :: "r"(adst + (uint32_t)i * 4096u), "l"(asrc + (size_t)i * 4096)
                         : "memory");
        }
        asm volatile("cp.async.commit_group;" ::: "memory");
    };

    auto load_scales = [&](int c) {
        int g = c >> 1;
        float4 s4 = *reinterpret_cast<const float4*>(sbase + (size_t)g * NF);
        float4 z4 = *reinterpret_cast<const float4*>(zbase + (size_t)g * NF);
        s01 = h2u(__floats2half2_rn(s4.x, s4.y)); s23 = h2u(__floats2half2_rn(s4.z, s4.w));
        z01 = h2u(__floats2half2_rn(z4.x, z4.y)); z23 = h2u(__floats2half2_rn(z4.z, z4.w));
    };

    auto ldg_b = [&](int c, int h) {           // rows k = kw + 8*(4h + j)
        const int* qp = qbase + (size_t)c * KC * NF + (size_t)(32 * h) * NF;
#pragma unroll
        for (int j = 0; j < 4; j++)
            bq4[j] = *reinterpret_cast<const int4*>(qp + (size_t)(kw + 8 * j) * NF);
    };

    auto store_b = [&](int st, int h) {
        const __half2 h1024 = u2h(0x64006400u);
        uint32_t base = sb + SM_B + (uint32_t)st * 16384u + sts_base + (uint32_t)h * 8192u;
#pragma unroll
        for (int j = 0; j < 4; j++) {
            uint32_t u01 = ((uint32_t)bq4[j].x | ((uint32_t)bq4[j].y << 16)) | 0x64006400u;
            uint32_t u23 = ((uint32_t)bq4[j].z | ((uint32_t)bq4[j].w << 16)) | 0x64006400u;
            __half2 q01 = __hsub2(u2h(u01), h1024);
            __half2 q23 = __hsub2(u2h(u23), h1024);
            uint32_t w01 = h2u(__hfma2(q01, u2h(s01), u2h(z01)));
            uint32_t w23 = h2u(__hfma2(q23, u2h(s23), u2h(z23)));
            asm volatile("st.shared.v2.b32 [%0], {%1,%2};"
                         :: "r"(base + (uint32_t)j * 2048u), "r"(w01), "r"(w23) : "memory");
        }
    };

    // One mb-pair of the chunk: fp16 chains over all 4 ks, flushed to fp32.
    auto compute_mbp = [&](int st, int mbp) {
        uint32_t abase = sb + SM_A + (uint32_t)st * 32768u;
        uint32_t bbase = sb + SM_B + (uint32_t)st * 16384u + b_row;

        uint32_t a[2][4][4];                 // [mi][ks][4]
#pragma unroll
        for (int mi = 0; mi < 2; mi++)
#pragma unroll
            for (int ks = 0; ks < 4; ks++)
                ldsm_x4(a[mi][ks],
                        abase + a_row[2 * mbp + mi] + ((((uint32_t)(2 * ks) + lq) ^ sx) << 4));

#pragma unroll
        for (int p = 0; p < 4; p++) {
            uint32_t bf[4][2][2];            // [ks][nj][2]
#pragma unroll
            for (int ks = 0; ks < 4; ks++)
                ldsm_x4_t(bf[ks][0][0], bf[ks][0][1], bf[ks][1][0], bf[ks][1][1],
                          bbase + (uint32_t)ks * 4096u + ((((uint32_t)(2 * p) + lq) ^ sx) << 4));

            uint32_t cc[2][2][2];            // [mi][nj][2] fp16 accums
#pragma unroll
            for (int mi = 0; mi < 2; mi++)
#pragma unroll
                for (int nj = 0; nj < 2; nj++) { cc[mi][nj][0] = 0u; cc[mi][nj][1] = 0u; }

#pragma unroll
            for (int ks = 0; ks < 4; ks++)
#pragma unroll
                for (int mi = 0; mi < 2; mi++)
#pragma unroll
                    for (int nj = 0; nj < 2; nj++)
                        mma16816_h(cc[mi][nj], a[mi][ks], bf[ks][nj][0], bf[ks][nj][1]);

#pragma unroll
            for (int mi = 0; mi < 2; mi++)
#pragma unroll
                for (int nj = 0; nj < 2; nj++) {
                    int mb = 2 * mbp + mi, nb = 2 * p + nj;
                    float2 f0 = __half22float2(u2h(cc[mi][nj][0]));
                    float2 f1 = __half22float2(u2h(cc[mi][nj][1]));
                    d[mb][nb][0] += f0.x; d[mb][nb][1] += f0.y;
                    d[mb][nb][2] += f1.x; d[mb][nb][3] += f1.y;
                }
        }
    };

    // ---- prologue: chunk 0 into stage 0 ----
    prefetch_a(0, 0);
    load_scales(0);
    ldg_b(0, 0); store_b(0, 0);
    ldg_b(0, 1); store_b(0, 1);
    asm volatile("cp.async.wait_group 0;" ::: "memory");
    __syncthreads();

    // ---- main loop (double buffered, R4 skeleton) ----
    for (int c = 0; c < NITER; c++) {
        int st = c & 1;
        if (c + 1 < NITER) {
            prefetch_a(c + 1, st ^ 1);
            load_scales(c + 1);
            ldg_b(c + 1, 0);
        }
        compute_mbp(st, 0);
        if (c + 1 < NITER) {
            store_b(st ^ 1, 0);
            ldg_b(c + 1, 1);
        }
        compute_mbp(st, 1);
        if (c + 1 < NITER) {
            store_b(st ^ 1, 1);
            asm volatile("cp.async.wait_group 0;" ::: "memory");
        }
        __syncthreads();
    }

    // ---- epilogue: accum + bias -> out ----
    const int gr = lane >> 2;
    const int c2 = (lane & 3) * 2;
#pragma unroll
    for (int mb = 0; mb < 4; mb++) {
        int m = wm * 64 + mb * 16 + gr;
#pragma unroll
        for (int nb = 0; nb < 8; nb++) {
            int n = n0 + wn * 64 + nb * 8 + c2;
            float2 bv = *reinterpret_cast<const float2*>(bias + n);
            float2 o0, o1;
            o0.x = d[mb][nb][0] + bv.x; o0.y = d[mb][nb][1] + bv.y;
            o1.x = d[mb][nb][2] + bv.x; o1.y = d[mb][nb][3] + bv.y;
            *reinterpret_cast<float2*>(out + (size_t)m * NF + n)       = o0;
            *reinterpret_cast<float2*>(out + (size_t)(m + 8) * NF + n) = o1;
        }
    }
}

// ---------------------------------------------------------------------------
// kernel_launch
// ---------------------------------------------------------------------------
extern "C" void kernel_launch(void* const* d_in, const int* in_sizes, int n_in,
                              void* d_out, int out_size) {
    const float* x    = (const float*)d_in[0];
    const int*   qk   = (const int*)d_in[1];
    const float* qs   = (const float*)d_in[2];
    const float* qzb  = (const float*)d_in[3];
    const float* bias = (const float*)d_in[4];
    float* out = (float*)d_out;

    cudaFuncSetAttribute(gemm_kernel, cudaFuncAttributeMaxDynamicSharedMemorySize, SM_TOTAL);

    prep_x_kernel<<<512, 256>>>(x);
    gemm_kernel<<<NCTA, 256, SM_TOTAL>>>(qk, qs, qzb, bias, out);
}

// round 12
// speedup vs baseline: 1.1292x; 1.1292x over previous
#include <cuda_runtime.h>
#include <cuda_fp16.h>
#include <cstdint>
#include <cstddef>

// ---------------------------------------------------------------------------
// Geometry
// ---------------------------------------------------------------------------
static constexpr int KF = 4096;
static constexpr int NF = 14336;
static constexpr int MROWS = 256;         // batch rows
static constexpr int NTILE = 128;
static constexpr int NCTA = NF / NTILE;   // 112
static constexpr int KC = 64;             // k per stage
static constexpr int NITER = KF / KC;     // 64

// fp16 image of x, pre-swizzled as the A smem tile image:
// 64 tiles (one per 64-k chunk), each 256 rows x 128B = 32KB.
__device__ __align__(128) unsigned char g_xs[64 * 32768];

// SMEM: A 2 x 32768 | rawB 2 x 32768 | fp16B 2 x 16384   (160KB, 1 CTA/SM)
static constexpr uint32_t SM_A    = 0;
static constexpr uint32_t SM_BRAW = 65536;
static constexpr uint32_t SM_BF16 = 131072;
static constexpr uint32_t SM_TOTAL = 163840;

// ---------------------------------------------------------------------------
// Helpers
// ---------------------------------------------------------------------------
__device__ __forceinline__ __half2 u2h(uint32_t u) { return *reinterpret_cast<__half2*>(&u); }
__device__ __forceinline__ uint32_t h2u(__half2 h) { return *reinterpret_cast<uint32_t*>(&h); }

__device__ __forceinline__ void ldsm_x4(uint32_t (&r)[4], uint32_t addr) {
    asm volatile("ldmatrix.sync.aligned.m8n8.x4.shared.b16 {%0,%1,%2,%3}, [%4];"
                 : "=r"(r[0]), "=r"(r[1]), "=r"(r[2]), "=r"(r[3]) : "r"(addr));
}
__device__ __forceinline__ void ldsm_x4_t(uint32_t& r0, uint32_t& r1, uint32_t& r2, uint32_t& r3,
                                          uint32_t addr) {
    asm volatile("ldmatrix.sync.aligned.m8n8.x4.trans.shared.b16 {%0,%1,%2,%3}, [%4];"
                 : "=r"(r0), "=r"(r1), "=r"(r2), "=r"(r3) : "r"(addr));
}
__device__ __forceinline__ void mma16816(float (&d)[4], const uint32_t (&a)[4],
                                         uint32_t b0, uint32_t b1) {
    asm volatile("mma.sync.aligned.m16n8k16.row.col.f32.f16.f16.f32 "
                 "{%0,%1,%2,%3}, {%4,%5,%6,%7}, {%8,%9}, {%0,%1,%2,%3};"
                 : "+f"(d[0]), "+f"(d[1]), "+f"(d[2]), "+f"(d[3])
                 : "r"(a[0]), "r"(a[1]), "r"(a[2]), "r"(a[3]), "r"(b0), "r"(b1));
}

// ---------------------------------------------------------------------------
// Kernel 1: x fp32 -> fp16 pre-swizzled A tile images. 8 k per thread.
// byte(m, kl) = m*128 + (((kl>>3)^(m&7))<<4) + (kl&7)*2
// ---------------------------------------------------------------------------
__global__ __launch_bounds__(256) void prep_x_kernel(const float* __restrict__ x) {
    int idx = blockIdx.x * 256 + threadIdx.x;      // 131072 threads
    int m   = idx >> 9;
    int kl8 = (idx & 511) * 8;
    const float* xp = x + (size_t)m * KF + kl8;
    float4 v0 = *reinterpret_cast<const float4*>(xp);
    float4 v1 = *reinterpret_cast<const float4*>(xp + 4);
    uint4 o;
    o.x = h2u(__floats2half2_rn(v0.x, v0.y));
    o.y = h2u(__floats2half2_rn(v0.z, v0.w));
    o.z = h2u(__floats2half2_rn(v1.x, v1.y));
    o.w = h2u(__floats2half2_rn(v1.z, v1.w));
    int c = kl8 >> 6, kl = kl8 & 63;
    uint32_t off = (uint32_t)m * 128u + ((((uint32_t)(kl >> 3)) ^ (uint32_t)(m & 7)) << 4);
    *reinterpret_cast<uint4*>(g_xs + (size_t)c * 32768 + off) = o;
}

// ---------------------------------------------------------------------------
// Kernel 2: GEMM. 112 CTAs x 256 threads, 1 CTA/SM.
// 8 warps as 4(m) x 2(n); warp tile 64x64; fp32 accumulation.
// B flows gmem --cp.async--> raw smem --LDS+dequant+STS--> fp16 smem.
// ---------------------------------------------------------------------------
__global__ __launch_bounds__(256, 1)
void gemm_kernel(const int* __restrict__ qk, const float* __restrict__ qs,
                 const float* __restrict__ qzb, const float* __restrict__ bias,
                 float* __restrict__ out) {
    extern __shared__ unsigned char smem[];
    const uint32_t sb = (uint32_t)__cvta_generic_to_shared(smem);
    const int t = threadIdx.x, lane = t & 31, w = t >> 5;
    const int wm = w >> 1, wn = w & 1;
    const int n0 = blockIdx.x * NTILE;

    // ---- B mapping: warp w covers rows k = w + 8j, lane covers 16B of n ----
    const uint32_t sts_base = (uint32_t)w * 256u
                            + ((uint32_t)((lane >> 1) ^ w) << 4) + (uint32_t)(lane & 1) * 8u;
    const uint32_t braw_off = (uint32_t)w * 512u + (uint32_t)lane * 16u;   // within raw tile
    const int* qsrc = qk + n0 + lane * 4;     // + (c*64 + w + 8i)*NF
    const float* sbase = qs  + n0 + lane * 4;
    const float* zbase = qzb + n0 + lane * 4;

    // ---- ldmatrix addressing ----
    const int l15 = lane & 15;
    const uint32_t sx = (uint32_t)(lane & 7);
    const uint32_t lq = (uint32_t)(lane >> 4);
    uint32_t a_row[4];
#pragma unroll
    for (int mb = 0; mb < 4; mb++)
        a_row[mb] = (uint32_t)(wm * 64 + mb * 16 + l15) * 128u;
    const uint32_t b_row = (uint32_t)l15 * 256u + (uint32_t)wn * 128u;

    float d[4][8][4];
#pragma unroll
    for (int mb = 0; mb < 4; mb++)
#pragma unroll
        for (int nb = 0; nb < 8; nb++)
#pragma unroll
            for (int i = 0; i < 4; i++) d[mb][nb][i] = 0.0f;

    uint32_t s01, s23, z01, z23;

    auto prefetch_a = [&](int c, int st) {
        const unsigned char* asrc = g_xs + (size_t)c * 32768 + (size_t)t * 16;
        uint32_t adst = sb + SM_A + (uint32_t)st * 32768u + (uint32_t)t * 16u;
#pragma unroll
        for (int i = 0; i < 8; i++) {
            asm volatile("cp.async.cg.shared.global [%0], [%1], 16;"
                         :: "r"(adst + (uint32_t)i * 4096u), "l"(asrc + (size_t)i * 4096)
                         : "memory");
        }
    };

    // raw B: 64 rows x 512B; this thread copies rows w+8i, its 16B n-slice
    auto prefetch_braw = [&](int c, int buf) {
        const int* src = qsrc + (size_t)(c * KC + w) * NF;
        uint32_t dst = sb + SM_BRAW + (uint32_t)buf * 32768u + braw_off;
#pragma unroll
        for (int i = 0; i < 8; i++) {
            asm volatile("cp.async.cg.shared.global [%0], [%1], 16;"
                         :: "r"(dst + (uint32_t)i * 4096u), "l"(src + (size_t)(8 * i) * NF)
                         : "memory");
        }
    };

    auto load_scales = [&](int c) {
        int g = c >> 1;
        float4 s4 = *reinterpret_cast<const float4*>(sbase + (size_t)g * NF);
        float4 z4 = *reinterpret_cast<const float4*>(zbase + (size_t)g * NF);
        s01 = h2u(__floats2half2_rn(s4.x, s4.y)); s23 = h2u(__floats2half2_rn(s4.z, s4.w));
        z01 = h2u(__floats2half2_rn(z4.x, z4.y)); z23 = h2u(__floats2half2_rn(z4.z, z4.w));
    };

    // dequant: raw[buf] -> fp16 tile[dst]; short-lived registers only
    auto dequant_store = [&](int buf, int dst) {
        const __half2 h1024 = u2h(0x64006400u);
        uint32_t rsrc = sb + SM_BRAW + (uint32_t)buf * 32768u + braw_off;
        uint32_t base = sb + SM_BF16 + (uint32_t)dst * 16384u + sts_base;
#pragma unroll
        for (int j = 0; j < 8; j++) {
            int4 q4;
            asm volatile("ld.shared.v4.b32 {%0,%1,%2,%3}, [%4];"
                         : "=r"(q4.x), "=r"(q4.y), "=r"(q4.z), "=r"(q4.w)
                         : "r"(rsrc + (uint32_t)j * 4096u));
            uint32_t u01 = ((uint32_t)q4.x | ((uint32_t)q4.y << 16)) | 0x64006400u;
            uint32_t u23 = ((uint32_t)q4.z | ((uint32_t)q4.w << 16)) | 0x64006400u;
            __half2 qa = __hsub2(u2h(u01), h1024);
            __half2 qb = __hsub2(u2h(u23), h1024);
            uint32_t w01 = h2u(__hfma2(qa, u2h(s01), u2h(z01)));
            uint32_t w23 = h2u(__hfma2(qb, u2h(s23), u2h(z23)));
            asm volatile("st.shared.v2.b32 [%0], {%1,%2};"
                         :: "r"(base + (uint32_t)j * 2048u), "r"(w01), "r"(w23) : "memory");
        }
    };

    auto compute_half = [&](int st, int h) {   // ks = 2h, 2h+1
        uint32_t abase = sb + SM_A + (uint32_t)st * 32768u;
        uint32_t bbase = sb + SM_BF16 + (uint32_t)st * 16384u + b_row;
#pragma unroll
        for (int ks = 2 * h; ks < 2 * h + 2; ks++) {
            uint32_t a[4][4];
#pragma unroll
            for (int mb = 0; mb < 4; mb++)
                ldsm_x4(a[mb], abase + a_row[mb] + ((((uint32_t)(2 * ks) + lq) ^ sx) << 4));
            uint32_t b[8][2];
#pragma unroll
            for (int p = 0; p < 4; p++)
                ldsm_x4_t(b[2 * p][0], b[2 * p][1], b[2 * p + 1][0], b[2 * p + 1][1],
                          bbase + (uint32_t)ks * 4096u + ((((uint32_t)(2 * p) + lq) ^ sx) << 4));
#pragma unroll
            for (int mb = 0; mb < 4; mb++)
#pragma unroll
                for (int nb = 0; nb < 8; nb++)
                    mma16816(d[mb][nb], a[mb], b[nb][0], b[nb][1]);
        }
    };

    // ---- prologue: A(0), raw(0), raw(1) in flight; dequant(0) ----
    prefetch_a(0, 0);
    prefetch_braw(0, 0);
    prefetch_braw(1, 1);
    asm volatile("cp.async.commit_group;" ::: "memory");
    load_scales(0);
    asm volatile("cp.async.wait_group 0;" ::: "memory");
    __syncthreads();
    dequant_store(0, 0);
    __syncthreads();

    // ---- main loop ----
    for (int c = 0; c < NITER; c++) {
        int st = c & 1;
        if (c + 1 < NITER) {
            prefetch_a(c + 1, st ^ 1);
            load_scales(c + 1);
        }
        if (c + 2 < NITER) prefetch_braw(c + 2, st);   // buffer (c+2)&1 == st
        asm volatile("cp.async.commit_group;" ::: "memory");
        compute_half(st, 0);
        if (c + 1 < NITER) dequant_store(st ^ 1, st ^ 1);
        compute_half(st, 1);
        asm volatile("cp.async.wait_group 0;" ::: "memory");
        __syncthreads();
    }

    // ---- epilogue: accum + bias -> out ----
    const int gr = lane >> 2;
    const int c2 = (lane & 3) * 2;
#pragma unroll
    for (int mb = 0; mb < 4; mb++) {
        int m = wm * 64 + mb * 16 + gr;
#pragma unroll
        for (int nb = 0; nb < 8; nb++) {
            int n = n0 + wn * 64 + nb * 8 + c2;
            float2 bv = *reinterpret_cast<const float2*>(bias + n);
            float2 o0, o1;
            o0.x = d[mb][nb][0] + bv.x; o0.y = d[mb][nb][1] + bv.y;
            o1.x = d[mb][nb][2] + bv.x; o1.y = d[mb][nb][3] + bv.y;
            *reinterpret_cast<float2*>(out + (size_t)m * NF + n)       = o0;
            *reinterpret_cast<float2*>(out + (size_t)(m + 8) * NF + n) = o1;
        }
    }
}

// ---------------------------------------------------------------------------
// kernel_launch
// ---------------------------------------------------------------------------
extern "C" void kernel_launch(void* const* d_in, const int* in_sizes, int n_in,
                              void* d_out, int out_size) {
    const float* x    = (const float*)d_in[0];
    const int*   qk   = (const int*)d_in[1];
    const float* qs   = (const float*)d_in[2];
    const float* qzb  = (const float*)d_in[3];
    const float* bias = (const float*)d_in[4];
    float* out = (float*)d_out;

    cudaFuncSetAttribute(gemm_kernel, cudaFuncAttributeMaxDynamicSharedMemorySize, SM_TOTAL);

    prep_x_kernel<<<512, 256>>>(x);
    gemm_kernel<<<NCTA, 256, SM_TOTAL>>>(qk, qs, qzb, bias, out);
}